// round 9
// baseline (speedup 1.0000x reference)
#include <cuda_runtime.h>
#include <math.h>
#include <stdint.h>

// Problem constants
#define B 4
#define NPTS 8192
#define HALF 4096
#define KNN 20
#define OCH 64
#define EPS 1e-5
#define SLOPE 0.2f
#define INFF __int_as_float(0x7f800000)

// k_knn_half dynamic smem: 4096 staged points + per-lane queues (depth 24)
#define PTS_BYTES (HALF * 16)                 // 64 KB
#define QDEPTH 24
#define BUF_BYTES (8 * 32 * QDEPTH * 8)       // 8 warps * 32 lanes * 24 * 8B = 48 KB
#define SMEM_TOTAL (PTS_BYTES + BUF_BYTES)    // 112 KB -> 2 blocks/SM

// Device scratch (no allocations allowed)
__device__ float2 g_part[B * 2 * NPTS * KNN];   // partial (d, j) lists, 10.5 MB
__device__ int    g_idx[B * NPTS * KNN];
__device__ double g_stats[B * 27];
__device__ float  g_mean[B * OCH];
__device__ float  g_rstd[B * OCH];

// ---------------------------------------------------------------------------
// Kernel 0: zero the moment accumulators (must happen every call)
// ---------------------------------------------------------------------------
__global__ void k_init() {
    int t = threadIdx.x;
    if (t < B * 27) g_stats[t] = 0.0;
}

// ---------------------------------------------------------------------------
// Branchless stable insertion into sorted-ascending (d, j) list of 20.
// Upper-bound placement (strict <): incoming value lands AFTER existing
// equal-d entries. Candidates arrive in ascending j, so ties are ordered by
// ascending j; evicted worst is the lexicographically largest (d, j)
// == jax top_k boundary semantics. Idempotent for vd = +INF.
// ---------------------------------------------------------------------------
__device__ __forceinline__ void insert_dj(float (&sd)[KNN], int (&sj)[KNN],
                                          float vd, int vj) {
    bool c[KNN];
#pragma unroll
    for (int k = 0; k < KNN; k++) c[k] = vd < sd[k];
#pragma unroll
    for (int k = KNN - 1; k >= 1; k--) {
        float td = c[k] ? vd : sd[k];
        int   tj = c[k] ? vj : sj[k];
        sd[k] = c[k - 1] ? sd[k - 1] : td;
        sj[k] = c[k - 1] ? sj[k - 1] : tj;
    }
    sd[0] = c[0] ? vd : sd[0];
    sj[0] = c[0] ? vj : sj[0];
}

// ---------------------------------------------------------------------------
// Kernel 1: half-sweep KNN. Block = 256 queries of one batch, sweeping one
// 4096-point half staged in 64 KB smem. 112 KB total -> 2 blocks/SM
// (4 warps/SMSP). Emits an exact sorted partial top-20 (d, j) list per query.
// Hot loop per 8-point group: phase 1 pure LDS+math, phase 2 predicated
// queue stores (PTX @p st, no BSSY), one uniform drain-check branch.
// ---------------------------------------------------------------------------
__global__ void __launch_bounds__(256, 2) k_knn_half(const float* __restrict__ x) {
    extern __shared__ char sm[];
    float4* s_pts = (float4*)sm;

    const int b = blockIdx.z;
    const int half = blockIdx.y;
    const int jbase = half * HALF;
    const float* xb = x + b * 3 * NPTS;

    // stage this half's points scaled {-2x,-2y,-2z, ||x||^2}
    for (int jj = threadIdx.x; jj < HALF; jj += 256) {
        int j = jbase + jj;
        float a0 = xb[j];
        float a1 = xb[NPTS + j];
        float a2 = xb[2 * NPTS + j];
        float sq = fmaf(a0, a0, fmaf(a1, a1, a2 * a2));
        s_pts[jj] = make_float4(-2.0f * a0, -2.0f * a1, -2.0f * a2, sq);
    }
    __syncthreads();

    const int tid = threadIdx.x;
    const int i = blockIdx.x * 256 + tid;      // query index
    // query coords from gmem (query may live in the other half)
    const float qx = xb[i], qy = xb[NPTS + i], qz = xb[2 * NPTS + i];
    const float qw = fmaf(qx, qx, fmaf(qy, qy, qz * qz));

    // lane-private queue: entry e at byte offset e*256 from bufA
    uint32_t sbase;
    asm("{ .reg .u64 t; cvta.to.shared.u64 t, %1; cvt.u32.u64 %0, t; }"
        : "=r"(sbase) : "l"(sm));
    const uint32_t bufA = sbase + (uint32_t)PTS_BYTES +
                          (uint32_t)(tid >> 5) * (32u * QDEPTH * 8u) +
                          (uint32_t)(tid & 31) * 8u;
    const float2* bufP = (const float2*)(sm + PTS_BYTES +
                          (tid >> 5) * (32 * QDEPTH * 8) + (tid & 31) * 8);

    float sd[KNN];
    int   sj[KNN];
#pragma unroll
    for (int k = 0; k < KNN; k++) { sd[k] = INFF; sj[k] = 0; }
    float worst = INFF;
    int   cnt = 0;

#define DRAIN() do {                                                   \
        for (int e = 0; __any_sync(0xffffffffu, e < cnt); e++) {       \
            float2 v = bufP[e * 32];                                   \
            float vd = (e < cnt) ? v.x : INFF;                         \
            insert_dj(sd, sj, vd, __float_as_int(v.y));                \
        }                                                              \
        worst = sd[KNN - 1];                                           \
        cnt = 0;                                                       \
    } while (0)

    for (int j0 = 0; j0 < HALF; j0 += 8) {
        // PHASE 1: pure loads + math (no asm in scope -> batched LDS.128)
        float dv[8];
#pragma unroll
        for (int u = 0; u < 8; u++) {
            float4 p = s_pts[j0 + u];
            dv[u] = fmaf(qz, p.z, fmaf(qy, p.y, fmaf(qx, p.x, qw + p.w)));
        }
        // PHASE 2: predicated queue stores (branch-free); j stored GLOBAL
#pragma unroll
        for (int u = 0; u < 8; u++) {
            bool t = dv[u] < worst;
            uint32_t a = bufA + (uint32_t)cnt * 256u;
            asm volatile(
                "{ .reg .pred p; setp.ne.u32 p, %0, 0;"
                "  @p st.shared.v2.b32 [%1], {%2, %3}; }"
                :: "r"((uint32_t)t), "r"(a), "r"(__float_as_int(dv[u])),
                   "r"(jbase + j0 + u)
                : "memory");
            cnt += t;
        }
        // cap proof: post-check cnt <= 15, +8 -> <= 23 < QDEPTH=24
        if (__any_sync(0xffffffffu, cnt >= 16)) DRAIN();
    }
    DRAIN();
#undef DRAIN

    // write sorted partial list (d, j-bits)
    float2* pp = g_part + (((size_t)b * 2 + half) * NPTS + i) * KNN;
#pragma unroll
    for (int k = 0; k < KNN; k++)
        pp[k] = make_float2(sd[k], __int_as_float(sj[k]));
}

// ---------------------------------------------------------------------------
// Kernel 2: merge the two partial lists per query (exact global top-20 with
// jax tie semantics), write g_idx, and accumulate the 27 per-batch moments.
// ---------------------------------------------------------------------------
__global__ void k_merge(const float* __restrict__ x) {
    __shared__ double sh[27];
    const int b = blockIdx.y;
    const int n = blockIdx.x * blockDim.x + threadIdx.x;
    const float* xb = x + b * 3 * NPTS;

    const float2* p0 = g_part + (((size_t)b * 2 + 0) * NPTS + n) * KNN;
    const float2* p1 = g_part + (((size_t)b * 2 + 1) * NPTS + n) * KNN;

    float sd[KNN];
    int   sj[KNN];
#pragma unroll
    for (int k = 0; k < KNN; k++) {
        float2 v = p0[k];
        sd[k] = v.x;
        sj[k] = __float_as_int(v.y);
    }
    // insert sorted high-half list: ties land after equal low-half entries
    // (all high-half j > low-half j) -> exact (d, j) lexicographic order
#pragma unroll
    for (int k = 0; k < KNN; k++) {
        float2 v = p1[k];
        insert_dj(sd, sj, v.x, __float_as_int(v.y));
    }

    int* op = g_idx + (b * NPTS + n) * KNN;
#pragma unroll
    for (int k = 0; k < KNN; k++) op[k] = sj[k];

    // ---------------- moment accumulation ----------------
    const float xi0 = xb[n], xi1 = xb[NPTS + n], xi2 = xb[2 * NPTS + n];
    float sd0 = 0.f, sd1 = 0.f, sd2 = 0.f;
    float s00 = 0.f, s01 = 0.f, s02 = 0.f, s11 = 0.f, s12 = 0.f, s22 = 0.f;
#pragma unroll
    for (int k = 0; k < KNN; k++) {
        int j = sj[k];
        float d0 = xb[j] - xi0;
        float d1 = xb[NPTS + j] - xi1;
        float d2 = xb[2 * NPTS + j] - xi2;
        sd0 += d0; sd1 += d1; sd2 += d2;
        s00 = fmaf(d0, d0, s00); s01 = fmaf(d0, d1, s01); s02 = fmaf(d0, d2, s02);
        s11 = fmaf(d1, d1, s11); s12 = fmaf(d1, d2, s12); s22 = fmaf(d2, d2, s22);
    }

    float v[27];
    v[0] = KNN * xi0; v[1] = KNN * xi1; v[2] = KNN * xi2;
    v[3] = sd0; v[4] = sd1; v[5] = sd2;
    v[6] = KNN * xi0 * xi0; v[7] = KNN * xi0 * xi1; v[8]  = KNN * xi0 * xi2;
    v[9] = KNN * xi1 * xi1; v[10] = KNN * xi1 * xi2; v[11] = KNN * xi2 * xi2;
    v[12] = xi0 * sd0; v[13] = xi0 * sd1; v[14] = xi0 * sd2;
    v[15] = xi1 * sd0; v[16] = xi1 * sd1; v[17] = xi1 * sd2;
    v[18] = xi2 * sd0; v[19] = xi2 * sd1; v[20] = xi2 * sd2;
    v[21] = s00; v[22] = s01; v[23] = s02; v[24] = s11; v[25] = s12; v[26] = s22;

#pragma unroll
    for (int q = 0; q < 27; q++) {
#pragma unroll
        for (int off = 16; off > 0; off >>= 1)
            v[q] += __shfl_down_sync(0xffffffffu, v[q], off);
    }

    if (threadIdx.x < 27) sh[threadIdx.x] = 0.0;
    __syncthreads();
    if ((threadIdx.x & 31) == 0) {
#pragma unroll
        for (int q = 0; q < 27; q++) atomicAdd(&sh[q], (double)v[q]);
    }
    __syncthreads();
    if (threadIdx.x < 27) atomicAdd(&g_stats[b * 27 + threadIdx.x], sh[threadIdx.x]);
}

// ---------------------------------------------------------------------------
// Kernel 3: per-(b,o) mean / rstd from the quadratic form.  256 threads.
// ---------------------------------------------------------------------------
__global__ void k_norm(const float* __restrict__ W) {
    int t = threadIdx.x;
    int b = t / OCH, o = t % OCH;
    const float* w = W + o * 6;
    double wa0 = w[0], wa1 = w[1], wa2 = w[2];
    double wb0 = w[3], wb1 = w[4], wb2 = w[5];
    const double* G = g_stats + b * 27;
    const double NK = (double)NPTS * (double)KNN;

    double mean = (wa0 * G[0] + wa1 * G[1] + wa2 * G[2] +
                   wb0 * G[3] + wb1 * G[4] + wb2 * G[5]) / NK;

    double xx = wa0 * wa0 * G[6] + 2.0 * wa0 * wa1 * G[7] + 2.0 * wa0 * wa2 * G[8] +
                wa1 * wa1 * G[9] + 2.0 * wa1 * wa2 * G[10] + wa2 * wa2 * G[11];
    double xd = wa0 * (wb0 * G[12] + wb1 * G[13] + wb2 * G[14]) +
                wa1 * (wb0 * G[15] + wb1 * G[16] + wb2 * G[17]) +
                wa2 * (wb0 * G[18] + wb1 * G[19] + wb2 * G[20]);
    double dd = wb0 * wb0 * G[21] + 2.0 * wb0 * wb1 * G[22] + 2.0 * wb0 * wb2 * G[23] +
                wb1 * wb1 * G[24] + 2.0 * wb1 * wb2 * G[25] + wb2 * wb2 * G[26];

    double Ey2 = (xx + 2.0 * xd + dd) / NK;
    double var = Ey2 - mean * mean;
    g_mean[t] = (float)mean;
    g_rstd[t] = (float)(1.0 / sqrt(var + EPS));
}

// ---------------------------------------------------------------------------
// Kernel 4: conv + max over k (monotone: normalize+leaky applied after max).
// ---------------------------------------------------------------------------
__global__ void k_out(const float* __restrict__ x, const float* __restrict__ W,
                      float* __restrict__ out) {
    const int b = blockIdx.y;
    const int n = blockIdx.x * blockDim.x + threadIdx.x;

    __shared__ float sW[OCH * 6];
    __shared__ float sM[OCH];
    __shared__ float sR[OCH];
    for (int t = threadIdx.x; t < OCH * 6; t += blockDim.x) sW[t] = W[t];
    if (threadIdx.x < OCH) {
        sM[threadIdx.x] = g_mean[b * OCH + threadIdx.x];
        sR[threadIdx.x] = g_rstd[b * OCH + threadIdx.x];
    }
    __syncthreads();

    const float* xb = x + b * 3 * NPTS;
    const float xi0 = xb[n], xi1 = xb[NPTS + n], xi2 = xb[2 * NPTS + n];
    const int* ip = g_idx + (b * NPTS + n) * KNN;

    float d0[KNN], d1[KNN], d2[KNN];
#pragma unroll
    for (int k = 0; k < KNN; k++) {
        int j = ip[k];
        d0[k] = xb[j] - xi0;
        d1[k] = xb[NPTS + j] - xi1;
        d2[k] = xb[2 * NPTS + j] - xi2;
    }

    float* ob = out + (size_t)b * OCH * NPTS + n;
    for (int o = 0; o < OCH; o++) {
        float wa0 = sW[o * 6 + 0], wa1 = sW[o * 6 + 1], wa2 = sW[o * 6 + 2];
        float wb0 = sW[o * 6 + 3], wb1 = sW[o * 6 + 4], wb2 = sW[o * 6 + 5];
        float p = wa0 * xi0;
        p = fmaf(wa1, xi1, p);
        p = fmaf(wa2, xi2, p);
        float m = -3.4e38f;
#pragma unroll
        for (int k = 0; k < KNN; k++) {
            float y = fmaf(wb2, d2[k], fmaf(wb1, d1[k], fmaf(wb0, d0[k], p)));
            m = fmaxf(m, y);
        }
        float z = (m - sM[o]) * sR[o];
        ob[(size_t)o * NPTS] = (z >= 0.f) ? z : SLOPE * z;
    }
}

// ---------------------------------------------------------------------------
extern "C" void kernel_launch(void* const* d_in, const int* in_sizes, int n_in,
                              void* d_out, int out_size) {
    const float* x = (const float*)d_in[0];   // [B, C, N]
    const float* W = (const float*)d_in[1];   // [O, 2C]
    float* out = (float*)d_out;               // [B, O, N]

    cudaFuncSetAttribute(k_knn_half, cudaFuncAttributeMaxDynamicSharedMemorySize,
                         SMEM_TOTAL);

    dim3 gknn(NPTS / 256, 2, B);   // (query chunk, point half, batch)
    dim3 grid(NPTS / 256, B);

    k_init<<<1, 128>>>();
    k_knn_half<<<gknn, 256, SMEM_TOTAL>>>(x);
    k_merge<<<grid, 256>>>(x);
    k_norm<<<1, B * OCH>>>(W);
    k_out<<<grid, 256>>>(x, W, out);
}